// round 3
// baseline (speedup 1.0000x reference)
#include <cuda_runtime.h>
#include <mma.h>
#include <math.h>

using namespace nvcuda;

#define BB 64
#define SS 1024
#define HH 1024
#define GG 4096
#define OO 128
#define NB 128

// Scratch (allocation-free rule: __device__ globals)
__device__ float g_gatesx[(size_t)SS * BB * GG];  // [S][B][4H], 1 GiB
__device__ float g_h[2][BB * HH];                 // double-buffered hidden state
__device__ unsigned g_bar;                        // cumulative grid-barrier counter

// ---------------------------------------------------------------------------
// Per-launch init (graph replays must be deterministic): h state + barrier.
// ---------------------------------------------------------------------------
__global__ void init_state(const float* __restrict__ h0) {
    int i = blockIdx.x * blockDim.x + threadIdx.x;
    if (i < BB * HH) g_h[0][i] = h0[i];
    if (i == 0) g_bar = 0u;
}

// ---------------------------------------------------------------------------
// Phase A: gates_x[s][b][g] = sum_k emb[x[b,s],k] * W_ih[g,k]
// Fused gather + tf32 wmma GEMM. Block tile 64(m) x 64(n), BK=32.
// grid = (64, 1024); 256 threads = 8 warps (2x4 of 32x16 output tiles)
// ---------------------------------------------------------------------------
__global__ void gatesx_kernel(const int* __restrict__ x,
                              const float* __restrict__ emb,
                              const float* __restrict__ Wih) {
    __shared__ float As[64][36];   // padded stride: kills bank-period aliasing
    __shared__ float Bs[64][36];

    int tid  = threadIdx.x;
    int warp = tid >> 5;
    int wm   = warp >> 2;   // 0..1
    int wn   = warp & 3;    // 0..3
    int m0   = blockIdx.y * 64;
    int n0   = blockIdx.x * 64;

    int lrow = tid >> 2;
    int lc   = (tid & 3) * 8;

    int sb = m0 + lrow;
    int s  = sb >> 6;
    int b  = sb & 63;
    const float* arow = emb + (size_t)x[b * SS + s] * HH;
    const float* brow = Wih + (size_t)(n0 + lrow) * HH;

    wmma::fragment<wmma::accumulator, 16, 16, 8, float> acc0, acc1;
    wmma::fill_fragment(acc0, 0.0f);
    wmma::fill_fragment(acc1, 0.0f);

    for (int kt = 0; kt < HH; kt += 32) {
        float4 a0 = *(const float4*)(arow + kt + lc);
        float4 a1 = *(const float4*)(arow + kt + lc + 4);
        float4 b0 = *(const float4*)(brow + kt + lc);
        float4 b1 = *(const float4*)(brow + kt + lc + 4);
        As[lrow][lc + 0] = wmma::__float_to_tf32(a0.x);
        As[lrow][lc + 1] = wmma::__float_to_tf32(a0.y);
        As[lrow][lc + 2] = wmma::__float_to_tf32(a0.z);
        As[lrow][lc + 3] = wmma::__float_to_tf32(a0.w);
        As[lrow][lc + 4] = wmma::__float_to_tf32(a1.x);
        As[lrow][lc + 5] = wmma::__float_to_tf32(a1.y);
        As[lrow][lc + 6] = wmma::__float_to_tf32(a1.z);
        As[lrow][lc + 7] = wmma::__float_to_tf32(a1.w);
        Bs[lrow][lc + 0] = wmma::__float_to_tf32(b0.x);
        Bs[lrow][lc + 1] = wmma::__float_to_tf32(b0.y);
        Bs[lrow][lc + 2] = wmma::__float_to_tf32(b0.z);
        Bs[lrow][lc + 3] = wmma::__float_to_tf32(b0.w);
        Bs[lrow][lc + 4] = wmma::__float_to_tf32(b1.x);
        Bs[lrow][lc + 5] = wmma::__float_to_tf32(b1.y);
        Bs[lrow][lc + 6] = wmma::__float_to_tf32(b1.z);
        Bs[lrow][lc + 7] = wmma::__float_to_tf32(b1.w);
        __syncthreads();

        #pragma unroll
        for (int kk = 0; kk < 32; kk += 8) {
            wmma::fragment<wmma::matrix_a, 16, 16, 8, wmma::precision::tf32, wmma::row_major> af0, af1;
            wmma::fragment<wmma::matrix_b, 16, 16, 8, wmma::precision::tf32, wmma::col_major> bf;
            wmma::load_matrix_sync(af0, &As[wm * 32][kk], 36);
            wmma::load_matrix_sync(af1, &As[wm * 32 + 16][kk], 36);
            wmma::load_matrix_sync(bf,  &Bs[wn * 16][kk], 36);
            wmma::mma_sync(acc0, af0, bf, acc0);
            wmma::mma_sync(acc1, af1, bf, acc1);
        }
        __syncthreads();
    }

    float* cp = g_gatesx + (size_t)(m0 + wm * 32) * GG + n0 + wn * 16;
    wmma::store_matrix_sync(cp, acc0, GG, wmma::mem_row_major);
    wmma::store_matrix_sync(cp + (size_t)16 * GG, acc1, GG, wmma::mem_row_major);
}

// ---------------------------------------------------------------------------
// Phase B: ONE persistent kernel for all 1024 steps + the fc epilogue.
// 128 CTAs x 256 threads, 1 CTA/SM (smem-bound) => all co-resident, so a
// software grid barrier (cumulative counter) is safe and graph-capturable.
// Each CTA owns 8 hidden units (32 W_hh rows resident in SMEM as tf32),
// c-state is CTA-private SMEM. h double-buffers through global; all h reads
// use __ldcg (L1 is stale across CTAs within one launch).
// ---------------------------------------------------------------------------
#define WS_STRIDE 1028
#define HS_STRIDE 36
#define SMEM_PERSIST ((32 * WS_STRIDE + 2 * 64 * HS_STRIDE + 64 * HS_STRIDE + 32 + 512) * 4)

__global__ __launch_bounds__(256, 1)
void lstm_persist(const float* __restrict__ Whh, const float* __restrict__ bih,
                  const float* __restrict__ bhh, const float* __restrict__ c0,
                  const float* __restrict__ fcW, const float* __restrict__ fcb,
                  float* __restrict__ out) {
    extern __shared__ float sm[];
    float* Ws   = sm;                              // [32][1028] tf32 W slice
    float* Hs   = Ws + 32 * WS_STRIDE;             // [2][64][36] h chunk (dbl buf)
    float* Cs   = Hs + 2 * 64 * HS_STRIDE;         // [64][36] gate pre-acts
    float* bsum = Cs + 64 * HS_STRIDE;             // [32] bih+bhh for own rows
    float* cst  = bsum + 32;                       // [512] private c state

    int tid  = threadIdx.x;
    int warp = tid >> 5;
    int lane = tid & 31;
    int wm   = warp >> 1;   // 0..3
    int wn   = warp & 1;    // 0..1
    int j0   = blockIdx.x * 8;

    // Load W slice (rows: gate g, unit j0+u -> W_hh row g*1024 + j0 + u) into SMEM
    for (int i = tid; i < 32 * 256; i += 256) {
        int r  = i >> 8;
        int k4 = (i & 255) << 2;
        float4 v = *(const float4*)(Whh + (size_t)((r >> 3) * HH + j0 + (r & 7)) * HH + k4);
        float* d = Ws + r * WS_STRIDE + k4;
        d[0] = wmma::__float_to_tf32(v.x);
        d[1] = wmma::__float_to_tf32(v.y);
        d[2] = wmma::__float_to_tf32(v.z);
        d[3] = wmma::__float_to_tf32(v.w);
    }
    if (tid < 32) {
        int col = (tid >> 3) * HH + j0 + (tid & 7);
        bsum[tid] = bih[col] + bhh[col];
    }
    for (int i = tid; i < 512; i += 256) {
        cst[i] = c0[(i >> 3) * HH + j0 + (i & 7)];
    }
    __syncthreads();

    int hrow = tid >> 2;
    int hc   = (tid & 3) << 3;

    for (int s = 0; s < SS; ++s) {
        const float* hin  = g_h[s & 1];
        float*       hout = g_h[(s & 1) ^ 1];
        const float* hrp  = hin + (size_t)hrow * HH + hc;

        wmma::fragment<wmma::accumulator, 16, 16, 8, float> acc;
        wmma::fill_fragment(acc, 0.0f);

        // prefetch chunk 0 (L2-only: L1 would be stale across CTAs)
        float4 va = __ldcg((const float4*)hrp);
        float4 vb = __ldcg((const float4*)(hrp + 4));

        for (int c = 0; c < 32; ++c) {
            float* hp = Hs + (c & 1) * (64 * HS_STRIDE) + hrow * HS_STRIDE + hc;
            hp[0] = wmma::__float_to_tf32(va.x);
            hp[1] = wmma::__float_to_tf32(va.y);
            hp[2] = wmma::__float_to_tf32(va.z);
            hp[3] = wmma::__float_to_tf32(va.w);
            hp[4] = wmma::__float_to_tf32(vb.x);
            hp[5] = wmma::__float_to_tf32(vb.y);
            hp[6] = wmma::__float_to_tf32(vb.z);
            hp[7] = wmma::__float_to_tf32(vb.w);
            __syncthreads();
            if (c < 31) {  // prefetch next chunk; LDG overlaps the MMAs below
                va = __ldcg((const float4*)(hrp + (c + 1) * 32));
                vb = __ldcg((const float4*)(hrp + (c + 1) * 32 + 4));
            }
            const float* hb = Hs + (c & 1) * (64 * HS_STRIDE);
            #pragma unroll
            for (int kk = 0; kk < 32; kk += 8) {
                wmma::fragment<wmma::matrix_a, 16, 16, 8, wmma::precision::tf32, wmma::row_major> af;
                wmma::fragment<wmma::matrix_b, 16, 16, 8, wmma::precision::tf32, wmma::col_major> bf;
                wmma::load_matrix_sync(af, hb + (wm * 16) * HS_STRIDE + kk, HS_STRIDE);
                wmma::load_matrix_sync(bf, Ws + (wn * 16) * WS_STRIDE + c * 32 + kk, WS_STRIDE);
                wmma::mma_sync(acc, af, bf, acc);
            }
        }

        wmma::store_matrix_sync(Cs + (wm * 16) * HS_STRIDE + wn * 16, acc, HS_STRIDE,
                                wmma::mem_row_major);
        __syncthreads();

        // Fused cell update for own 8 units x 64 batch
        const float* gx = g_gatesx + (size_t)s * BB * GG;
        for (int cell = tid; cell < 512; cell += 256) {
            int m = cell >> 3;
            int u = cell & 7;
            int col = j0 + u;
            const float* gxm = gx + (size_t)m * GG;
            float ip = Cs[m * HS_STRIDE + u]      + __ldcs(gxm + col)          + bsum[u];
            float fp = Cs[m * HS_STRIDE + 8 + u]  + __ldcs(gxm + HH + col)     + bsum[8 + u];
            float gp = Cs[m * HS_STRIDE + 16 + u] + __ldcs(gxm + 2 * HH + col) + bsum[16 + u];
            float op = Cs[m * HS_STRIDE + 24 + u] + __ldcs(gxm + 3 * HH + col) + bsum[24 + u];
            float ig = 1.0f / (1.0f + expf(-ip));
            float fg = 1.0f / (1.0f + expf(-fp));
            float gg = tanhf(gp);
            float og = 1.0f / (1.0f + expf(-op));
            float cc = fg * cst[cell] + ig * gg;
            cst[cell] = cc;
            hout[m * HH + col] = og * tanhf(cc);
        }

        // Grid barrier: release own h writes, arrive, spin on cumulative count
        __threadfence();
        __syncthreads();
        if (tid == 0) {
            atomicAdd(&g_bar, 1u);
            unsigned target = (unsigned)(s + 1) * NB;
            while (*(volatile unsigned*)&g_bar < target) __nanosleep(64);
        }
        __syncthreads();
    }

    // fc epilogue: h_last is in g_h[0] after 1024 steps. 1024 warps, 8 outs each.
    int gw = blockIdx.x * 8 + warp;
    for (int i = gw; i < BB * OO; i += NB * 8) {
        int b = i >> 7;
        int o = i & 127;
        const float* hb = g_h[0] + (size_t)b * HH;
        const float* wo = fcW + (size_t)o * HH;
        float sum = 0.0f;
        for (int k = lane; k < HH; k += 32) sum += __ldcg(hb + k) * wo[k];
        #pragma unroll
        for (int d = 16; d; d >>= 1) sum += __shfl_down_sync(0xffffffffu, sum, d);
        if (lane == 0) out[i] = sum + fcb[o];
    }
}

// ---------------------------------------------------------------------------
extern "C" void kernel_launch(void* const* d_in, const int* in_sizes, int n_in,
                              void* d_out, int out_size) {
    const int*   x   = (const int*)  d_in[0];
    const float* emb = (const float*)d_in[1];
    const float* Wih = (const float*)d_in[2];
    const float* Whh = (const float*)d_in[3];
    const float* bih = (const float*)d_in[4];
    const float* bhh = (const float*)d_in[5];
    const float* fcW = (const float*)d_in[6];
    const float* fcb = (const float*)d_in[7];
    const float* h0  = (const float*)d_in[8];
    const float* c0  = (const float*)d_in[9];
    float* out = (float*)d_out;

    init_state<<<256, 256>>>(h0);
    gatesx_kernel<<<dim3(64, 1024), 256>>>(x, emb, Wih);
    cudaFuncSetAttribute(lstm_persist, cudaFuncAttributeMaxDynamicSharedMemorySize,
                         SMEM_PERSIST);
    lstm_persist<<<NB, 256, SMEM_PERSIST>>>(Whh, bih, bhh, c0, fcW, fcb, out);
}

// round 10
// speedup vs baseline: 1.0714x; 1.0714x over previous
#include <cuda_runtime.h>
#include <mma.h>
#include <math.h>
#include <cstdint>

using namespace nvcuda;

#define BB 64
#define SS 1024
#define HH 1024
#define GG 4096
#define OO 128
#define NB 128

// Scratch (allocation-free rule: __device__ globals)
__device__ float g_gatesx[(size_t)SS * BB * GG];  // [S][B][4H], 1 GiB
__device__ float g_h[2][BB * HH];                 // double-buffered hidden state
__device__ unsigned g_bar;                        // cumulative grid-barrier counter

// ---------------------------------------------------------------------------
__global__ void init_state(const float* __restrict__ h0) {
    int i = blockIdx.x * blockDim.x + threadIdx.x;
    if (i < BB * HH) g_h[0][i] = h0[i];
    if (i == 0) g_bar = 0u;
}

// ---------------------------------------------------------------------------
// Phase A: gates_x[s][b][g] = sum_k emb[x[b,s],k] * W_ih[g,k]   (tf32 RN wmma)
// ---------------------------------------------------------------------------
__global__ void gatesx_kernel(const int* __restrict__ x,
                              const float* __restrict__ emb,
                              const float* __restrict__ Wih) {
    __shared__ float As[64][36];
    __shared__ float Bs[64][36];

    int tid  = threadIdx.x;
    int warp = tid >> 5;
    int wm   = warp >> 2;
    int wn   = warp & 3;
    int m0   = blockIdx.y * 64;
    int n0   = blockIdx.x * 64;

    int lrow = tid >> 2;
    int lc   = (tid & 3) * 8;

    int sb = m0 + lrow;
    int s  = sb >> 6;
    int b  = sb & 63;
    const float* arow = emb + (size_t)x[b * SS + s] * HH;
    const float* brow = Wih + (size_t)(n0 + lrow) * HH;

    wmma::fragment<wmma::accumulator, 16, 16, 8, float> acc0, acc1;
    wmma::fill_fragment(acc0, 0.0f);
    wmma::fill_fragment(acc1, 0.0f);

    for (int kt = 0; kt < HH; kt += 32) {
        float4 a0 = *(const float4*)(arow + kt + lc);
        float4 a1 = *(const float4*)(arow + kt + lc + 4);
        float4 b0 = *(const float4*)(brow + kt + lc);
        float4 b1 = *(const float4*)(brow + kt + lc + 4);
        As[lrow][lc + 0] = wmma::__float_to_tf32(a0.x);
        As[lrow][lc + 1] = wmma::__float_to_tf32(a0.y);
        As[lrow][lc + 2] = wmma::__float_to_tf32(a0.z);
        As[lrow][lc + 3] = wmma::__float_to_tf32(a0.w);
        As[lrow][lc + 4] = wmma::__float_to_tf32(a1.x);
        As[lrow][lc + 5] = wmma::__float_to_tf32(a1.y);
        As[lrow][lc + 6] = wmma::__float_to_tf32(a1.z);
        As[lrow][lc + 7] = wmma::__float_to_tf32(a1.w);
        Bs[lrow][lc + 0] = wmma::__float_to_tf32(b0.x);
        Bs[lrow][lc + 1] = wmma::__float_to_tf32(b0.y);
        Bs[lrow][lc + 2] = wmma::__float_to_tf32(b0.z);
        Bs[lrow][lc + 3] = wmma::__float_to_tf32(b0.w);
        Bs[lrow][lc + 4] = wmma::__float_to_tf32(b1.x);
        Bs[lrow][lc + 5] = wmma::__float_to_tf32(b1.y);
        Bs[lrow][lc + 6] = wmma::__float_to_tf32(b1.z);
        Bs[lrow][lc + 7] = wmma::__float_to_tf32(b1.w);
        __syncthreads();

        #pragma unroll
        for (int kk = 0; kk < 32; kk += 8) {
            wmma::fragment<wmma::matrix_a, 16, 16, 8, wmma::precision::tf32, wmma::row_major> af0, af1;
            wmma::fragment<wmma::matrix_b, 16, 16, 8, wmma::precision::tf32, wmma::col_major> bf;
            wmma::load_matrix_sync(af0, &As[wm * 32][kk], 36);
            wmma::load_matrix_sync(af1, &As[wm * 32 + 16][kk], 36);
            wmma::load_matrix_sync(bf,  &Bs[wn * 16][kk], 36);
            wmma::mma_sync(acc0, af0, bf, acc0);
            wmma::mma_sync(acc1, af1, bf, acc1);
        }
        __syncthreads();
    }

    float* cp = g_gatesx + (size_t)(m0 + wm * 32) * GG + n0 + wn * 16;
    wmma::store_matrix_sync(cp, acc0, GG, wmma::mem_row_major);
    wmma::store_matrix_sync(cp + (size_t)16 * GG, acc1, GG, wmma::mem_row_major);
}

// ---------------------------------------------------------------------------
// Phase B persistent kernel
// ---------------------------------------------------------------------------
#define WS_STRIDE 1028
#define CH_STRIDE 68
#define CHUNK_F   (64 * CH_STRIDE)
#define NPIPE     4
#define NCH       16
#define CS_STRIDE 36
#define SMEM_PERSIST ((32 * WS_STRIDE + NPIPE * CHUNK_F + 64 * CS_STRIDE + 32 + 512) * 4)

__device__ __forceinline__ float fsig(float x) {
    return __fdividef(1.0f, 1.0f + __expf(-x));
}
__device__ __forceinline__ float ftanh(float x) {
    return 1.0f - __fdividef(2.0f, __expf(2.0f * x) + 1.0f);
}

__device__ __forceinline__ void stage_chunk(unsigned int hs_base,
                                            const float* __restrict__ hin,
                                            int hrow, int hc16, int c) {
    const float* src = hin + (size_t)hrow * HH + c * 64 + hc16;
    unsigned int d = hs_base + (unsigned int)((c & 3) * CHUNK_F + hrow * CH_STRIDE + hc16) * 4u;
    #pragma unroll
    for (int i = 0; i < 4; i++)
        asm volatile("cp.async.cg.shared.global [%0], [%1], 16;"
                     :: "r"(d + 16u * i), "l"(src + 4 * i));
    asm volatile("cp.async.commit_group;");
}

__global__ __launch_bounds__(256, 1)
void lstm_persist(const float* __restrict__ Whh, const float* __restrict__ bih,
                  const float* __restrict__ bhh, const float* __restrict__ c0,
                  const float* __restrict__ fcW, const float* __restrict__ fcb,
                  float* __restrict__ out) {
    extern __shared__ float sm[];
    float* Ws   = sm;                           // [32][1028] tf32 W slice
    float* Hs   = Ws + 32 * WS_STRIDE;          // [NPIPE][64][68] h chunks
    float* Cs   = Hs + NPIPE * CHUNK_F;         // [64][36] gate pre-acts
    float* bsum = Cs + 64 * CS_STRIDE;          // [32]
    float* cst  = bsum + 32;                    // [512] private c state

    int tid  = threadIdx.x;
    int warp = tid >> 5;
    int lane = tid & 31;
    int wm   = warp >> 1;   // 0..3
    int wn   = warp & 1;    // 0..1
    int j0   = blockIdx.x * 8;

    unsigned int hs_base = (unsigned int)__cvta_generic_to_shared(Hs);

    // Load W slice (gate g, unit j0+u -> W_hh row g*1024 + j0 + u), RN-converted
    for (int i = tid; i < 32 * 256; i += 256) {
        int r  = i >> 8;
        int k4 = (i & 255) << 2;
        float4 v = *(const float4*)(Whh + (size_t)((r >> 3) * HH + j0 + (r & 7)) * HH + k4);
        float* d = Ws + r * WS_STRIDE + k4;
        d[0] = wmma::__float_to_tf32(v.x);
        d[1] = wmma::__float_to_tf32(v.y);
        d[2] = wmma::__float_to_tf32(v.z);
        d[3] = wmma::__float_to_tf32(v.w);
    }
    if (tid < 32) {
        int col = (tid >> 3) * HH + j0 + (tid & 7);
        bsum[tid] = bih[col] + bhh[col];
    }
    for (int i = tid; i < 512; i += 256) {
        cst[i] = c0[(i >> 3) * HH + j0 + (i & 7)];
    }
    __syncthreads();

    int hrow = tid >> 2;
    int hc16 = (tid & 3) << 4;

    bool alive = true;   // set false only on barrier-starvation bailout

    for (int s = 0; s < SS && alive; ++s) {
        const float* hin  = g_h[s & 1];
        float*       hout = g_h[(s & 1) ^ 1];

        // Hoist gates_x loads: issue now, consume after GEMM (DRAM latency hidden)
        float gxa[2][4];
        const float* gx = g_gatesx + (size_t)s * BB * GG;
        #pragma unroll
        for (int ii = 0; ii < 2; ii++) {
            int cell = tid + ii * 256;
            const float* gxm = gx + (size_t)(cell >> 3) * GG + j0 + (cell & 7);
            #pragma unroll
            for (int g = 0; g < 4; g++) gxa[ii][g] = __ldcs(gxm + g * HH);
        }

        // Pipeline prologue
        #pragma unroll
        for (int c = 0; c < NPIPE - 1; c++) stage_chunk(hs_base, hin, hrow, hc16, c);

        wmma::fragment<wmma::accumulator, 16, 16, 8, float> acc;
        wmma::fill_fragment(acc, 0.0f);

        for (int c = 0; c < NCH; ++c) {
            asm volatile("cp.async.wait_group %0;" :: "n"(NPIPE - 2));
            __syncthreads();
            if (c + NPIPE - 1 < NCH) stage_chunk(hs_base, hin, hrow, hc16, c + NPIPE - 1);
            const float* hb = Hs + (c & 3) * CHUNK_F;
            #pragma unroll
            for (int kk = 0; kk < 64; kk += 8) {
                wmma::fragment<wmma::matrix_a, 16, 16, 8, wmma::precision::tf32, wmma::row_major> af;
                wmma::fragment<wmma::matrix_b, 16, 16, 8, wmma::precision::tf32, wmma::col_major> bf;
                wmma::load_matrix_sync(af, hb + (wm * 16) * CH_STRIDE + kk, CH_STRIDE);
                wmma::load_matrix_sync(bf, Ws + (wn * 16) * WS_STRIDE + c * 64 + kk, WS_STRIDE);
                wmma::mma_sync(acc, af, bf, acc);
            }
        }
        // drain remaining cp.async groups before reusing buffers next step
        asm volatile("cp.async.wait_group 0;");

        wmma::store_matrix_sync(Cs + (wm * 16) * CS_STRIDE + wn * 16, acc, CS_STRIDE,
                                wmma::mem_row_major);
        __syncthreads();

        // Fused cell update (fast activations; MUFU-based)
        #pragma unroll
        for (int ii = 0; ii < 2; ii++) {
            int cell = tid + ii * 256;
            int m = cell >> 3;
            int u = cell & 7;
            float ip = Cs[m * CS_STRIDE + u]      + gxa[ii][0] + bsum[u];
            float fp = Cs[m * CS_STRIDE + 8 + u]  + gxa[ii][1] + bsum[8 + u];
            float gp = Cs[m * CS_STRIDE + 16 + u] + gxa[ii][2] + bsum[16 + u];
            float op = Cs[m * CS_STRIDE + 24 + u] + gxa[ii][3] + bsum[24 + u];
            float ig = fsig(ip);
            float fg = fsig(fp);
            float gg = ftanh(gp);
            float og = fsig(op);
            float cc = fg * cst[cell] + ig * gg;
            cst[cell] = cc;
            hout[m * HH + j0 + u] = og * ftanh(cc);
        }

        // Grid barrier — EXACT R3-proven sequence, plus a bounded spin so any
        // starvation becomes an observable failure instead of a container hang.
        __threadfence();
        __syncthreads();
        if (tid == 0) {
            atomicAdd(&g_bar, 1u);
            unsigned target = (unsigned)(s + 1) * NB;
            long long guard = 0;
            while (*(volatile unsigned*)&g_bar < target) {
                __nanosleep(64);
                if (++guard > (64ll << 20)) { g_bar = 0xC0000000u; break; }
            }
            if (*(volatile unsigned*)&g_bar >= 0xC0000000u) ((volatile float*)Cs)[0] = -1e30f;
        }
        __syncthreads();
        if (Cs[0] == -1e30f) alive = false;   // uniform exit, no deadlock
        __syncthreads();
    }

    // fc epilogue: h_last in g_h[0]
    int gw = blockIdx.x * 8 + warp;
    for (int i = gw; i < BB * OO; i += NB * 8) {
        int b = i >> 7;
        int o = i & 127;
        const float* hb = g_h[0] + (size_t)b * HH;
        const float* wo = fcW + (size_t)o * HH;
        float sum = 0.0f;
        for (int k = lane; k < HH; k += 32) sum += __ldcg(hb + k) * wo[k];
        #pragma unroll
        for (int d = 16; d; d >>= 1) sum += __shfl_down_sync(0xffffffffu, sum, d);
        if (lane == 0) out[i] = sum + fcb[o];
    }
}

// ---------------------------------------------------------------------------
extern "C" void kernel_launch(void* const* d_in, const int* in_sizes, int n_in,
                              void* d_out, int out_size) {
    const int*   x   = (const int*)  d_in[0];
    const float* emb = (const float*)d_in[1];
    const float* Wih = (const float*)d_in[2];
    const float* Whh = (const float*)d_in[3];
    const float* bih = (const float*)d_in[4];
    const float* bhh = (const float*)d_in[5];
    const float* fcW = (const float*)d_in[6];
    const float* fcb = (const float*)d_in[7];
    const float* h0  = (const float*)d_in[8];
    const float* c0  = (const float*)d_in[9];
    float* out = (float*)d_out;

    init_state<<<256, 256>>>(h0);
    gatesx_kernel<<<dim3(64, 1024), 256>>>(x, emb, Wih);
    cudaFuncSetAttribute(lstm_persist, cudaFuncAttributeMaxDynamicSharedMemorySize,
                         SMEM_PERSIST);
    lstm_persist<<<NB, 256, SMEM_PERSIST>>>(Whh, bih, bhh, c0, fcW, fcb, out);
}

// round 12
// speedup vs baseline: 1.1629x; 1.0854x over previous
#include <cuda_runtime.h>
#include <mma.h>
#include <math.h>
#include <cstdint>

using namespace nvcuda;

#define BB 64
#define SS 1024
#define HH 1024
#define GG 4096
#define OO 128
#define NB 128

// Scratch (allocation-free rule: __device__ globals)
__device__ float g_gatesx[(size_t)SS * BB * GG];  // [S][B][4H], 1 GiB
__device__ float g_h[2][BB * HH];                 // double-buffered hidden state
__device__ unsigned g_bar;                        // cumulative grid-barrier counter

// ---------------------------------------------------------------------------
// Phase A: gates_x[s][b][g] = sum_k emb[x[b,s],k] * W_ih[g,k]   (tf32 RN wmma)
// CTA(0,0) additionally performs the per-launch state init (h0 copy + barrier
// reset) so the whole run is 2 launches and ncu's capture slot must land on
// either this kernel or lstm_persist.
// ---------------------------------------------------------------------------
__global__ void gatesx_kernel(const int* __restrict__ x,
                              const float* __restrict__ emb,
                              const float* __restrict__ Wih,
                              const float* __restrict__ h0) {
    __shared__ float As[64][36];
    __shared__ float Bs[64][36];

    int tid  = threadIdx.x;
    int warp = tid >> 5;
    int wm   = warp >> 2;
    int wn   = warp & 3;
    int m0   = blockIdx.y * 64;
    int n0   = blockIdx.x * 64;

    // Per-launch init (graph replays deterministic): done by CTA(0,0)
    if (m0 == 0 && n0 == 0) {
        const float4* src = (const float4*)h0;
        float4* dst = (float4*)g_h[0];
        for (int i = tid; i < BB * HH / 4; i += 256) dst[i] = src[i];
        if (tid == 0) g_bar = 0u;
    }

    int lrow = tid >> 2;
    int lc   = (tid & 3) * 8;

    int sb = m0 + lrow;
    int s  = sb >> 6;
    int b  = sb & 63;
    const float* arow = emb + (size_t)x[b * SS + s] * HH;
    const float* brow = Wih + (size_t)(n0 + lrow) * HH;

    wmma::fragment<wmma::accumulator, 16, 16, 8, float> acc0, acc1;
    wmma::fill_fragment(acc0, 0.0f);
    wmma::fill_fragment(acc1, 0.0f);

    for (int kt = 0; kt < HH; kt += 32) {
        float4 a0 = *(const float4*)(arow + kt + lc);
        float4 a1 = *(const float4*)(arow + kt + lc + 4);
        float4 b0 = *(const float4*)(brow + kt + lc);
        float4 b1 = *(const float4*)(brow + kt + lc + 4);
        As[lrow][lc + 0] = wmma::__float_to_tf32(a0.x);
        As[lrow][lc + 1] = wmma::__float_to_tf32(a0.y);
        As[lrow][lc + 2] = wmma::__float_to_tf32(a0.z);
        As[lrow][lc + 3] = wmma::__float_to_tf32(a0.w);
        As[lrow][lc + 4] = wmma::__float_to_tf32(a1.x);
        As[lrow][lc + 5] = wmma::__float_to_tf32(a1.y);
        As[lrow][lc + 6] = wmma::__float_to_tf32(a1.z);
        As[lrow][lc + 7] = wmma::__float_to_tf32(a1.w);
        Bs[lrow][lc + 0] = wmma::__float_to_tf32(b0.x);
        Bs[lrow][lc + 1] = wmma::__float_to_tf32(b0.y);
        Bs[lrow][lc + 2] = wmma::__float_to_tf32(b0.z);
        Bs[lrow][lc + 3] = wmma::__float_to_tf32(b0.w);
        Bs[lrow][lc + 4] = wmma::__float_to_tf32(b1.x);
        Bs[lrow][lc + 5] = wmma::__float_to_tf32(b1.y);
        Bs[lrow][lc + 6] = wmma::__float_to_tf32(b1.z);
        Bs[lrow][lc + 7] = wmma::__float_to_tf32(b1.w);
        __syncthreads();

        #pragma unroll
        for (int kk = 0; kk < 32; kk += 8) {
            wmma::fragment<wmma::matrix_a, 16, 16, 8, wmma::precision::tf32, wmma::row_major> af0, af1;
            wmma::fragment<wmma::matrix_b, 16, 16, 8, wmma::precision::tf32, wmma::col_major> bf;
            wmma::load_matrix_sync(af0, &As[wm * 32][kk], 36);
            wmma::load_matrix_sync(af1, &As[wm * 32 + 16][kk], 36);
            wmma::load_matrix_sync(bf,  &Bs[wn * 16][kk], 36);
            wmma::mma_sync(acc0, af0, bf, acc0);
            wmma::mma_sync(acc1, af1, bf, acc1);
        }
        __syncthreads();
    }

    float* cp = g_gatesx + (size_t)(m0 + wm * 32) * GG + n0 + wn * 16;
    wmma::store_matrix_sync(cp, acc0, GG, wmma::mem_row_major);
    wmma::store_matrix_sync(cp + (size_t)16 * GG, acc1, GG, wmma::mem_row_major);
}

// ---------------------------------------------------------------------------
// Phase B persistent kernel.
// GEMM retile: 8-way K-split. Each warp owns K-slice {c*64 + ks*8 .. +8} for
// all 16 chunks and computes the FULL 64x32 output into 8 independent
// accumulators (kills the single-acc RAW chain, halves LDS traffic).
// Partials go to SMEM (aliased over the h-pipe buffers) and are reduced
// per-thread straight into the fused cell update.
// ---------------------------------------------------------------------------
#define WS_STRIDE 1028
#define CH_STRIDE 68
#define CHUNK_F   (64 * CH_STRIDE)
#define NPIPE     4
#define NCH       16
#define SMEM_PERSIST ((32 * WS_STRIDE + NPIPE * CHUNK_F + 32 + 512 + 4) * 4)

__device__ __forceinline__ float fsig(float x) {
    return __fdividef(1.0f, 1.0f + __expf(-x));
}
__device__ __forceinline__ float ftanh(float x) {
    return 1.0f - __fdividef(2.0f, __expf(2.0f * x) + 1.0f);
}

__device__ __forceinline__ void stage_chunk(unsigned int hs_base,
                                            const float* __restrict__ hin,
                                            int hrow, int hc16, int c) {
    const float* src = hin + (size_t)hrow * HH + c * 64 + hc16;
    unsigned int d = hs_base + (unsigned int)((c & 3) * CHUNK_F + hrow * CH_STRIDE + hc16) * 4u;
    #pragma unroll
    for (int i = 0; i < 4; i++)
        asm volatile("cp.async.cg.shared.global [%0], [%1], 16;"
                     :: "r"(d + 16u * i), "l"(src + 4 * i));
    asm volatile("cp.async.commit_group;");
}

__global__ __launch_bounds__(256, 1)
void lstm_persist(const float* __restrict__ Whh, const float* __restrict__ bih,
                  const float* __restrict__ bhh, const float* __restrict__ c0,
                  const float* __restrict__ fcW, const float* __restrict__ fcb,
                  float* __restrict__ out) {
    extern __shared__ float sm[];
    float* Ws    = sm;                          // [32][1028] tf32 W slice
    float* Hs    = Ws + 32 * WS_STRIDE;         // [NPIPE][64][68] h chunks
    float* Gpart = Hs;                          // aliased: [8][64*32] partials
    float* bsum  = Hs + NPIPE * CHUNK_F;        // [32]
    float* cst   = bsum + 32;                   // [512] private c state
    float* flag  = cst + 512;                   // [1] starvation flag

    int tid  = threadIdx.x;
    int warp = tid >> 5;    // = K-slice id (0..7)
    int lane = tid & 31;
    int j0   = blockIdx.x * 8;

    unsigned int hs_base = (unsigned int)__cvta_generic_to_shared(Hs);

    // Load W slice (gate g, unit j0+u -> W_hh row g*1024 + j0 + u), RN-converted
    for (int i = tid; i < 32 * 256; i += 256) {
        int r  = i >> 8;
        int k4 = (i & 255) << 2;
        float4 v = *(const float4*)(Whh + (size_t)((r >> 3) * HH + j0 + (r & 7)) * HH + k4);
        float* d = Ws + r * WS_STRIDE + k4;
        d[0] = wmma::__float_to_tf32(v.x);
        d[1] = wmma::__float_to_tf32(v.y);
        d[2] = wmma::__float_to_tf32(v.z);
        d[3] = wmma::__float_to_tf32(v.w);
    }
    if (tid < 32) {
        int col = (tid >> 3) * HH + j0 + (tid & 7);
        bsum[tid] = bih[col] + bhh[col];
    }
    if (tid == 0) flag[0] = 0.0f;
    for (int i = tid; i < 512; i += 256) {
        cst[i] = c0[(i >> 3) * HH + j0 + (i & 7)];
    }
    __syncthreads();

    int hrow = tid >> 2;
    int hc16 = (tid & 3) << 4;

    bool alive = true;

    for (int s = 0; s < SS && alive; ++s) {
        const float* hin  = g_h[s & 1];
        float*       hout = g_h[(s & 1) ^ 1];

        // Hoist gates_x loads: issue now, consume after GEMM
        float gxa[2][4];
        const float* gx = g_gatesx + (size_t)s * BB * GG;
        #pragma unroll
        for (int ii = 0; ii < 2; ii++) {
            int cell = tid + ii * 256;
            const float* gxm = gx + (size_t)(cell >> 3) * GG + j0 + (cell & 7);
            #pragma unroll
            for (int g = 0; g < 4; g++) gxa[ii][g] = __ldcs(gxm + g * HH);
        }

        // Pipeline prologue
        #pragma unroll
        for (int c = 0; c < NPIPE - 1; c++) stage_chunk(hs_base, hin, hrow, hc16, c);

        wmma::fragment<wmma::accumulator, 16, 16, 8, float> acc[4][2];
        #pragma unroll
        for (int mi = 0; mi < 4; mi++)
            #pragma unroll
            for (int ni = 0; ni < 2; ni++) wmma::fill_fragment(acc[mi][ni], 0.0f);

        int kks = warp * 8;   // this warp's K-offset within each 64-chunk

        for (int c = 0; c < NCH; ++c) {
            asm volatile("cp.async.wait_group %0;" :: "n"(NPIPE - 2));
            __syncthreads();
            if (c + NPIPE - 1 < NCH) stage_chunk(hs_base, hin, hrow, hc16, c + NPIPE - 1);
            const float* hb = Hs + (c & 3) * CHUNK_F + kks;
            const float* wb = Ws + c * 64 + kks;

            wmma::fragment<wmma::matrix_a, 16, 16, 8, wmma::precision::tf32, wmma::row_major> af[4];
            wmma::fragment<wmma::matrix_b, 16, 16, 8, wmma::precision::tf32, wmma::col_major> bf[2];
            #pragma unroll
            for (int mi = 0; mi < 4; mi++)
                wmma::load_matrix_sync(af[mi], hb + (mi * 16) * CH_STRIDE, CH_STRIDE);
            #pragma unroll
            for (int ni = 0; ni < 2; ni++)
                wmma::load_matrix_sync(bf[ni], wb + (ni * 16) * WS_STRIDE, WS_STRIDE);
            #pragma unroll
            for (int mi = 0; mi < 4; mi++)
                #pragma unroll
                for (int ni = 0; ni < 2; ni++)
                    wmma::mma_sync(acc[mi][ni], af[mi], bf[ni], acc[mi][ni]);
        }
        asm volatile("cp.async.wait_group 0;");
        __syncthreads();   // all warps done reading Hs before Gpart overwrites it

        // Store per-warp 64x32 partials (row-major, ldm=32)
        float* gp = Gpart + warp * (64 * 32);
        #pragma unroll
        for (int mi = 0; mi < 4; mi++)
            #pragma unroll
            for (int ni = 0; ni < 2; ni++)
                wmma::store_matrix_sync(gp + (mi * 16) * 32 + ni * 16, acc[mi][ni], 32,
                                        wmma::mem_row_major);
        __syncthreads();

        // Per-thread K-reduction + fused cell update (2 cells/thread)
        #pragma unroll
        for (int ii = 0; ii < 2; ii++) {
            int cell = tid + ii * 256;
            int m = cell >> 3;
            int u = cell & 7;
            float pre[4];
            #pragma unroll
            for (int g = 0; g < 4; g++) pre[g] = gxa[ii][g] + bsum[g * 8 + u];
            #pragma unroll
            for (int w = 0; w < 8; w++) {
                const float* p = Gpart + w * (64 * 32) + m * 32 + u;
                #pragma unroll
                for (int g = 0; g < 4; g++) pre[g] += p[g * 8];
            }
            float ig = fsig(pre[0]);
            float fg = fsig(pre[1]);
            float gg = ftanh(pre[2]);
            float og = fsig(pre[3]);
            float cc = fg * cst[cell] + ig * gg;
            cst[cell] = cc;
            hout[m * HH + j0 + u] = og * ftanh(cc);
        }

        // Grid barrier (R3-proven) + bounded spin
        __threadfence();
        __syncthreads();
        if (tid == 0) {
            atomicAdd(&g_bar, 1u);
            unsigned target = (unsigned)(s + 1) * NB;
            long long guard = 0;
            while (*(volatile unsigned*)&g_bar < target) {
                __nanosleep(64);
                if (++guard > (64ll << 20)) { g_bar = 0xC0000000u; break; }
            }
            if (*(volatile unsigned*)&g_bar >= 0xC0000000u) flag[0] = 1.0f;
        }
        __syncthreads();
        if (flag[0] != 0.0f) alive = false;
        __syncthreads();
    }

    // fc epilogue: h_last in g_h[0]
    int gw = blockIdx.x * 8 + warp;
    for (int i = gw; i < BB * OO; i += NB * 8) {
        int b = i >> 7;
        int o = i & 127;
        const float* hb = g_h[0] + (size_t)b * HH;
        const float* wo = fcW + (size_t)o * HH;
        float sum = 0.0f;
        for (int k = lane; k < HH; k += 32) sum += __ldcg(hb + k) * wo[k];
        #pragma unroll
        for (int d = 16; d; d >>= 1) sum += __shfl_down_sync(0xffffffffu, sum, d);
        if (lane == 0) out[i] = sum + fcb[o];
    }
}

// ---------------------------------------------------------------------------
extern "C" void kernel_launch(void* const* d_in, const int* in_sizes, int n_in,
                              void* d_out, int out_size) {
    const int*   x   = (const int*)  d_in[0];
    const float* emb = (const float*)d_in[1];
    const float* Wih = (const float*)d_in[2];
    const float* Whh = (const float*)d_in[3];
    const float* bih = (const float*)d_in[4];
    const float* bhh = (const float*)d_in[5];
    const float* fcW = (const float*)d_in[6];
    const float* fcb = (const float*)d_in[7];
    const float* h0  = (const float*)d_in[8];
    const float* c0  = (const float*)d_in[9];
    float* out = (float*)d_out;

    gatesx_kernel<<<dim3(64, 1024), 256>>>(x, emb, Wih, h0);
    cudaFuncSetAttribute(lstm_persist, cudaFuncAttributeMaxDynamicSharedMemorySize,
                         SMEM_PERSIST);
    lstm_persist<<<NB, 256, SMEM_PERSIST>>>(Whh, bih, bhh, c0, fcW, fcb, out);
}

// round 14
// speedup vs baseline: 1.1948x; 1.0274x over previous
#include <cuda_runtime.h>
#include <mma.h>
#include <math.h>
#include <cstdint>

using namespace nvcuda;

#define BB 64
#define SS 1024
#define HH 1024
#define GG 4096
#define OO 128
#define NB 128
#define VV 32000

// Scratch (allocation-free rule: __device__ globals)
__device__ float g_gatesx[(size_t)SS * BB * GG];  // [S][B][4H], 1 GiB
__device__ float g_embT[(size_t)VV * HH];         // tf32-RN preconverted emb
__device__ float g_wihT[(size_t)GG * HH];         // tf32-RN preconverted W_ih
__device__ float g_h[2][BB * HH];                 // double-buffered hidden state
__device__ unsigned g_bar;                        // cumulative grid-barrier counter

// ---------------------------------------------------------------------------
// Pre-pass: RN-convert emb and W_ih to tf32 once (~300MB traffic, ~40us)
// ---------------------------------------------------------------------------
__global__ void preconvert(const float* __restrict__ emb,
                           const float* __restrict__ Wih) {
    size_t i0 = (size_t)blockIdx.x * blockDim.x + threadIdx.x;
    size_t stride = (size_t)gridDim.x * blockDim.x;
    for (size_t k = i0; k < (size_t)VV * HH; k += stride)
        g_embT[k] = wmma::__float_to_tf32(emb[k]);
    for (size_t k = i0; k < (size_t)GG * HH; k += stride)
        g_wihT[k] = wmma::__float_to_tf32(Wih[k]);
}

// ---------------------------------------------------------------------------
// Phase A: gates_x[s][b][g] = sum_k emb[x[b,s],k] * W_ih[g,k]
// 128x128x32 tiles, cp.async 2-stage pipeline, 2 CTAs/SM.
// CTA(0,0) also does the per-launch state init (h0 copy + barrier reset).
// ---------------------------------------------------------------------------
#define GX_TS   36                       // padded float stride (144B, 16B-aligned)
#define GX_TILE (128 * GX_TS)            // floats per (A or B) tile
#define GX_STG  (2 * GX_TILE)            // floats per stage (A + B)
#define SMEM_GX (2 * GX_STG * 4)         // bytes: 2 stages

__device__ __forceinline__ void gx_stage(unsigned int sgb,
                                         const float* __restrict__ arow,
                                         const float* __restrict__ brow,
                                         int r, int hf, int kt) {
    unsigned int abase = sgb + (unsigned int)((kt & 1) * GX_STG + r * GX_TS + hf) * 4u;
    unsigned int bbase = abase + (unsigned int)GX_TILE * 4u;
    const float* asrc = arow + kt * 32 + hf;
    const float* bsrc = brow + kt * 32 + hf;
    #pragma unroll
    for (int i = 0; i < 4; i++) {
        asm volatile("cp.async.cg.shared.global [%0], [%1], 16;"
                     :: "r"(abase + 16u * i), "l"(asrc + 4 * i));
        asm volatile("cp.async.cg.shared.global [%0], [%1], 16;"
                     :: "r"(bbase + 16u * i), "l"(bsrc + 4 * i));
    }
    asm volatile("cp.async.commit_group;");
}

__global__ __launch_bounds__(256, 2)
void gatesx_kernel(const int* __restrict__ x, const float* __restrict__ h0) {
    extern __shared__ float sg[];

    int tid  = threadIdx.x;
    int warp = tid >> 5;
    int wm   = warp >> 2;   // 0..1  (64 rows each)
    int wn   = warp & 3;    // 0..3  (32 cols each)
    int m0   = blockIdx.y * 128;
    int n0   = blockIdx.x * 128;

    // Per-launch init (graph replays deterministic): CTA(0,0)
    if (blockIdx.x == 0 && blockIdx.y == 0) {
        const float4* src = (const float4*)h0;
        float4* dst = (float4*)g_h[0];
        for (int i = tid; i < BB * HH / 4; i += 256) dst[i] = src[i];
        if (tid == 0) g_bar = 0u;
    }

    // Staging assignment: thread -> (row r = tid>>1, half hf = (tid&1)*16 floats)
    int r  = tid >> 1;
    int hf = (tid & 1) * 16;

    int sb = m0 + r;
    int s  = sb >> 6;
    int b  = sb & 63;
    const float* arow = g_embT + (size_t)x[b * SS + s] * HH;
    const float* brow = g_wihT + (size_t)(n0 + r) * HH;

    unsigned int sgb = (unsigned int)__cvta_generic_to_shared(sg);

    wmma::fragment<wmma::accumulator, 16, 16, 8, float> acc[4][2];
    #pragma unroll
    for (int mi = 0; mi < 4; mi++)
        #pragma unroll
        for (int ni = 0; ni < 2; ni++) wmma::fill_fragment(acc[mi][ni], 0.0f);

    gx_stage(sgb, arow, brow, r, hf, 0);

    for (int c = 0; c < 32; ++c) {
        asm volatile("cp.async.wait_group 0;");
        __syncthreads();
        if (c + 1 < 32) gx_stage(sgb, arow, brow, r, hf, c + 1);

        const float* As = sg + (c & 1) * GX_STG;
        const float* Bs = As + GX_TILE;
        #pragma unroll
        for (int kk = 0; kk < 32; kk += 8) {
            wmma::fragment<wmma::matrix_a, 16, 16, 8, wmma::precision::tf32, wmma::row_major> af[4];
            wmma::fragment<wmma::matrix_b, 16, 16, 8, wmma::precision::tf32, wmma::col_major> bf[2];
            #pragma unroll
            for (int mi = 0; mi < 4; mi++)
                wmma::load_matrix_sync(af[mi], As + (wm * 64 + mi * 16) * GX_TS + kk, GX_TS);
            #pragma unroll
            for (int ni = 0; ni < 2; ni++)
                wmma::load_matrix_sync(bf[ni], Bs + (wn * 32 + ni * 16) * GX_TS + kk, GX_TS);
            #pragma unroll
            for (int mi = 0; mi < 4; mi++)
                #pragma unroll
                for (int ni = 0; ni < 2; ni++)
                    wmma::mma_sync(acc[mi][ni], af[mi], bf[ni], acc[mi][ni]);
        }
        __syncthreads();
    }

    #pragma unroll
    for (int mi = 0; mi < 4; mi++)
        #pragma unroll
        for (int ni = 0; ni < 2; ni++) {
            float* cp = g_gatesx + (size_t)(m0 + wm * 64 + mi * 16) * GG
                        + n0 + wn * 32 + ni * 16;
            wmma::store_matrix_sync(cp, acc[mi][ni], GG, wmma::mem_row_major);
        }
}

// ---------------------------------------------------------------------------
// Phase B persistent kernel (unchanged from R12 — proven at 3.96e-4)
// ---------------------------------------------------------------------------
#define WS_STRIDE 1028
#define CH_STRIDE 68
#define CHUNK_F   (64 * CH_STRIDE)
#define NPIPE     4
#define NCH       16
#define SMEM_PERSIST ((32 * WS_STRIDE + NPIPE * CHUNK_F + 32 + 512 + 4) * 4)

__device__ __forceinline__ float fsig(float x) {
    return __fdividef(1.0f, 1.0f + __expf(-x));
}
__device__ __forceinline__ float ftanh(float x) {
    return 1.0f - __fdividef(2.0f, __expf(2.0f * x) + 1.0f);
}

__device__ __forceinline__ void stage_chunk(unsigned int hs_base,
                                            const float* __restrict__ hin,
                                            int hrow, int hc16, int c) {
    const float* src = hin + (size_t)hrow * HH + c * 64 + hc16;
    unsigned int d = hs_base + (unsigned int)((c & 3) * CHUNK_F + hrow * CH_STRIDE + hc16) * 4u;
    #pragma unroll
    for (int i = 0; i < 4; i++)
        asm volatile("cp.async.cg.shared.global [%0], [%1], 16;"
                     :: "r"(d + 16u * i), "l"(src + 4 * i));
    asm volatile("cp.async.commit_group;");
}

__global__ __launch_bounds__(256, 1)
void lstm_persist(const float* __restrict__ Whh, const float* __restrict__ bih,
                  const float* __restrict__ bhh, const float* __restrict__ c0,
                  const float* __restrict__ fcW, const float* __restrict__ fcb,
                  float* __restrict__ out) {
    extern __shared__ float sm[];
    float* Ws    = sm;                          // [32][1028] tf32 W slice
    float* Hs    = Ws + 32 * WS_STRIDE;         // [NPIPE][64][68] h chunks
    float* Gpart = Hs;                          // aliased: [8][64*32] partials
    float* bsum  = Hs + NPIPE * CHUNK_F;        // [32]
    float* cst   = bsum + 32;                   // [512] private c state
    float* flag  = cst + 512;                   // [1] starvation flag

    int tid  = threadIdx.x;
    int warp = tid >> 5;    // K-slice id (0..7)
    int lane = tid & 31;
    int j0   = blockIdx.x * 8;

    unsigned int hs_base = (unsigned int)__cvta_generic_to_shared(Hs);

    for (int i = tid; i < 32 * 256; i += 256) {
        int r  = i >> 8;
        int k4 = (i & 255) << 2;
        float4 v = *(const float4*)(Whh + (size_t)((r >> 3) * HH + j0 + (r & 7)) * HH + k4);
        float* d = Ws + r * WS_STRIDE + k4;
        d[0] = wmma::__float_to_tf32(v.x);
        d[1] = wmma::__float_to_tf32(v.y);
        d[2] = wmma::__float_to_tf32(v.z);
        d[3] = wmma::__float_to_tf32(v.w);
    }
    if (tid < 32) {
        int col = (tid >> 3) * HH + j0 + (tid & 7);
        bsum[tid] = bih[col] + bhh[col];
    }
    if (tid == 0) flag[0] = 0.0f;
    for (int i = tid; i < 512; i += 256) {
        cst[i] = c0[(i >> 3) * HH + j0 + (i & 7)];
    }
    __syncthreads();

    int hrow = tid >> 2;
    int hc16 = (tid & 3) << 4;

    bool alive = true;

    for (int s = 0; s < SS && alive; ++s) {
        const float* hin  = g_h[s & 1];
        float*       hout = g_h[(s & 1) ^ 1];

        float gxa[2][4];
        const float* gx = g_gatesx + (size_t)s * BB * GG;
        #pragma unroll
        for (int ii = 0; ii < 2; ii++) {
            int cell = tid + ii * 256;
            const float* gxm = gx + (size_t)(cell >> 3) * GG + j0 + (cell & 7);
            #pragma unroll
            for (int g = 0; g < 4; g++) gxa[ii][g] = __ldcs(gxm + g * HH);
        }

        #pragma unroll
        for (int c = 0; c < NPIPE - 1; c++) stage_chunk(hs_base, hin, hrow, hc16, c);

        wmma::fragment<wmma::accumulator, 16, 16, 8, float> acc[4][2];
        #pragma unroll
        for (int mi = 0; mi < 4; mi++)
            #pragma unroll
            for (int ni = 0; ni < 2; ni++) wmma::fill_fragment(acc[mi][ni], 0.0f);

        int kks = warp * 8;

        for (int c = 0; c < NCH; ++c) {
            asm volatile("cp.async.wait_group %0;" :: "n"(NPIPE - 2));
            __syncthreads();
            if (c + NPIPE - 1 < NCH) stage_chunk(hs_base, hin, hrow, hc16, c + NPIPE - 1);
            const float* hb = Hs + (c & 3) * CHUNK_F + kks;
            const float* wb = Ws + c * 64 + kks;

            wmma::fragment<wmma::matrix_a, 16, 16, 8, wmma::precision::tf32, wmma::row_major> af[4];
            wmma::fragment<wmma::matrix_b, 16, 16, 8, wmma::precision::tf32, wmma::col_major> bf[2];
            #pragma unroll
            for (int mi = 0; mi < 4; mi++)
                wmma::load_matrix_sync(af[mi], hb + (mi * 16) * CH_STRIDE, CH_STRIDE);
            #pragma unroll
            for (int ni = 0; ni < 2; ni++)
                wmma::load_matrix_sync(bf[ni], wb + (ni * 16) * WS_STRIDE, WS_STRIDE);
            #pragma unroll
            for (int mi = 0; mi < 4; mi++)
                #pragma unroll
                for (int ni = 0; ni < 2; ni++)
                    wmma::mma_sync(acc[mi][ni], af[mi], bf[ni], acc[mi][ni]);
        }
        asm volatile("cp.async.wait_group 0;");
        __syncthreads();

        float* gp = Gpart + warp * (64 * 32);
        #pragma unroll
        for (int mi = 0; mi < 4; mi++)
            #pragma unroll
            for (int ni = 0; ni < 2; ni++)
                wmma::store_matrix_sync(gp + (mi * 16) * 32 + ni * 16, acc[mi][ni], 32,
                                        wmma::mem_row_major);
        __syncthreads();

        #pragma unroll
        for (int ii = 0; ii < 2; ii++) {
            int cell = tid + ii * 256;
            int m = cell >> 3;
            int u = cell & 7;
            float pre[4];
            #pragma unroll
            for (int g = 0; g < 4; g++) pre[g] = gxa[ii][g] + bsum[g * 8 + u];
            #pragma unroll
            for (int w = 0; w < 8; w++) {
                const float* p = Gpart + w * (64 * 32) + m * 32 + u;
                #pragma unroll
                for (int g = 0; g < 4; g++) pre[g] += p[g * 8];
            }
            float ig = fsig(pre[0]);
            float fg = fsig(pre[1]);
            float gg = ftanh(pre[2]);
            float og = fsig(pre[3]);
            float cc = fg * cst[cell] + ig * gg;
            cst[cell] = cc;
            hout[m * HH + j0 + u] = og * ftanh(cc);
        }

        __threadfence();
        __syncthreads();
        if (tid == 0) {
            atomicAdd(&g_bar, 1u);
            unsigned target = (unsigned)(s + 1) * NB;
            long long guard = 0;
            while (*(volatile unsigned*)&g_bar < target) {
                __nanosleep(64);
                if (++guard > (64ll << 20)) { g_bar = 0xC0000000u; break; }
            }
            if (*(volatile unsigned*)&g_bar >= 0xC0000000u) flag[0] = 1.0f;
        }
        __syncthreads();
        if (flag[0] != 0.0f) alive = false;
        __syncthreads();
    }

    // fc epilogue: h_last in g_h[0]
    int gw = blockIdx.x * 8 + warp;
    for (int i = gw; i < BB * OO; i += NB * 8) {
        int b = i >> 7;
        int o = i & 127;
        const float* hb = g_h[0] + (size_t)b * HH;
        const float* wo = fcW + (size_t)o * HH;
        float sum = 0.0f;
        for (int k = lane; k < HH; k += 32) sum += __ldcg(hb + k) * wo[k];
        #pragma unroll
        for (int d = 16; d; d >>= 1) sum += __shfl_down_sync(0xffffffffu, sum, d);
        if (lane == 0) out[i] = sum + fcb[o];
    }
}

// ---------------------------------------------------------------------------
extern "C" void kernel_launch(void* const* d_in, const int* in_sizes, int n_in,
                              void* d_out, int out_size) {
    const int*   x   = (const int*)  d_in[0];
    const float* emb = (const float*)d_in[1];
    const float* Wih = (const float*)d_in[2];
    const float* Whh = (const float*)d_in[3];
    const float* bih = (const float*)d_in[4];
    const float* bhh = (const float*)d_in[5];
    const float* fcW = (const float*)d_in[6];
    const float* fcb = (const float*)d_in[7];
    const float* h0  = (const float*)d_in[8];
    const float* c0  = (const float*)d_in[9];
    float* out = (float*)d_out;

    preconvert<<<2048, 256>>>(emb, Wih);
    cudaFuncSetAttribute(gatesx_kernel, cudaFuncAttributeMaxDynamicSharedMemorySize,
                         SMEM_GX);
    gatesx_kernel<<<dim3(32, 512), 256, SMEM_GX>>>(x, h0);
    cudaFuncSetAttribute(lstm_persist, cudaFuncAttributeMaxDynamicSharedMemorySize,
                         SMEM_PERSIST);
    lstm_persist<<<NB, 256, SMEM_PERSIST>>>(Whh, bih, bhh, c0, fcW, fcb, out);
}